// round 1
// baseline (speedup 1.0000x reference)
#include <cuda_runtime.h>
#include <math.h>

#define N_NODES 100000
#define N_EDGES 1600000
#define C_IN 128
#define HID 128
#define N_LAYERS 4
#define N_GRAPHS 512
#define N_OUT 10
#define BN_EPS 1e-5f

// ---------------- scratch (static device allocations; no runtime alloc) ----
__device__ float g_agg[(size_t)N_NODES * C_IN];       // 51.2 MB
__device__ float g_h1[(size_t)N_NODES * 2 * HID];     // 102.4 MB
__device__ float g_x0[(size_t)N_NODES * HID];         // 51.2 MB
__device__ float g_x1[(size_t)N_NODES * HID];         // 51.2 MB
__device__ float g_pooled[N_GRAPHS * HID];            // 256 KB

// ---------------- zero ----------------
__global__ void k_zero(float4* __restrict__ p, int n4) {
    int i = blockIdx.x * blockDim.x + threadIdx.x;
    if (i < n4) p[i] = make_float4(0.f, 0.f, 0.f, 0.f);
}

// ---------------- edge aggregation: agg[dst] += x[src] --------------------
// warp per edge; 128 floats = 32 lanes x float4; vectorized reduction.
__global__ void k_aggregate(const float* __restrict__ x,
                            const int* __restrict__ src,
                            const int* __restrict__ dst,
                            float* __restrict__ agg) {
    int w = (blockIdx.x * blockDim.x + threadIdx.x) >> 5;
    if (w >= N_EDGES) return;
    int lane = threadIdx.x & 31;
    int s = __ldg(src + w);
    int d = __ldg(dst + w);
    float4 v = ((const float4*)(x + (size_t)s * C_IN))[lane];
    float4* o = ((float4*)(agg + (size_t)d * C_IN)) + lane;
    asm volatile("red.global.add.v4.f32 [%0], {%1,%2,%3,%4};"
                 :: "l"(o), "f"(v.x), "f"(v.y), "f"(v.z), "f"(v.w)
                 : "memory");
}

// ---------------- graph pooling: pooled[batch[n]] += x[n] -----------------
__global__ void k_pool(const float* __restrict__ x,
                       const int* __restrict__ batch,
                       float* __restrict__ pooled) {
    int w = (blockIdx.x * blockDim.x + threadIdx.x) >> 5;
    if (w >= N_NODES) return;
    int lane = threadIdx.x & 31;
    int g = __ldg(batch + w);
    float4 v = ((const float4*)(x + (size_t)w * HID))[lane];
    float4* o = ((float4*)(pooled + (size_t)g * HID)) + lane;
    asm volatile("red.global.add.v4.f32 [%0], {%1,%2,%3,%4};"
                 :: "l"(o), "f"(v.x), "f"(v.y), "f"(v.z), "f"(v.w)
                 : "memory");
}

// ---------------- fused GEMM + bias + BN + ReLU ----------------------------
// out[M,N] = relu(bn( A' @ W + bias ))
// If AGG != nullptr: A' = (1+eps)*A + AGG  (GIN node update), else A' = A.
// Tiling: BM=BN=128, BK=16, 256 threads, 8x8 microtile (FMA-bound).
__global__ __launch_bounds__(256, 2)
void k_gemm_bn_relu(const float* __restrict__ A,
                    const float* __restrict__ AGG,
                    const float* __restrict__ epsp,
                    const float* __restrict__ W,
                    const float* __restrict__ bias,
                    const float* __restrict__ bng, const float* __restrict__ bnb,
                    const float* __restrict__ bnm, const float* __restrict__ bnv,
                    float* __restrict__ out, int M, int N, int K) {
    const int BM = 128, BN = 128, BK = 16;
    __shared__ float As[BK][BM + 1];  // transposed A tile, +1 to dodge conflicts
    __shared__ float Bs[BK][BN];

    int tid = threadIdx.x;
    int tx = tid & 15;       // column group (8 cols)
    int ty = tid >> 4;       // row group (8 rows)
    int m0 = blockIdx.x * BM;
    int n0 = blockIdx.y * BN;

    float epsv = (AGG != nullptr) ? (1.0f + __ldg(epsp)) : 0.0f;

    float acc[8][8];
#pragma unroll
    for (int i = 0; i < 8; i++)
#pragma unroll
        for (int j = 0; j < 8; j++) acc[i][j] = 0.f;

    for (int k0 = 0; k0 < K; k0 += BK) {
        // --- load A tile (BM x BK), store transposed ---
#pragma unroll
        for (int i = 0; i < 2; i++) {
            int idx4 = tid + i * 256;          // 512 float4s
            int r = idx4 >> 2;                 // 0..127 row in tile
            int kc = (idx4 & 3) << 2;          // 0,4,8,12
            int row = m0 + r;
            float4 v = make_float4(0.f, 0.f, 0.f, 0.f);
            if (row < M) {
                v = *(const float4*)(A + (size_t)row * K + k0 + kc);
                if (AGG != nullptr) {
                    float4 gg = *(const float4*)(AGG + (size_t)row * K + k0 + kc);
                    v.x = fmaf(v.x, epsv, gg.x);
                    v.y = fmaf(v.y, epsv, gg.y);
                    v.z = fmaf(v.z, epsv, gg.z);
                    v.w = fmaf(v.w, epsv, gg.w);
                }
            }
            As[kc + 0][r] = v.x;
            As[kc + 1][r] = v.y;
            As[kc + 2][r] = v.z;
            As[kc + 3][r] = v.w;
        }
        // --- load B tile (BK x BN) ---
#pragma unroll
        for (int i = 0; i < 2; i++) {
            int idx4 = tid + i * 256;
            int kr = idx4 >> 5;                // 0..15
            int nc = (idx4 & 31) << 2;         // 0..124
            *(float4*)(&Bs[kr][nc]) =
                *(const float4*)(W + (size_t)(k0 + kr) * N + n0 + nc);
        }
        __syncthreads();

#pragma unroll
        for (int kk = 0; kk < BK; kk++) {
            float a[8], b[8];
#pragma unroll
            for (int i = 0; i < 8; i++) a[i] = As[kk][ty * 8 + i];
            float4 b0 = *(const float4*)(&Bs[kk][tx * 8]);
            float4 b1 = *(const float4*)(&Bs[kk][tx * 8 + 4]);
            b[0] = b0.x; b[1] = b0.y; b[2] = b0.z; b[3] = b0.w;
            b[4] = b1.x; b[5] = b1.y; b[6] = b1.z; b[7] = b1.w;
#pragma unroll
            for (int i = 0; i < 8; i++)
#pragma unroll
                for (int j = 0; j < 8; j++) acc[i][j] = fmaf(a[i], b[j], acc[i][j]);
        }
        __syncthreads();
    }

    // --- epilogue: bias + BN + ReLU ---
    float sc[8], sh[8];
#pragma unroll
    for (int j = 0; j < 8; j++) {
        int c = n0 + tx * 8 + j;
        float s = __ldg(bng + c) * rsqrtf(__ldg(bnv + c) + BN_EPS);
        sc[j] = s;
        sh[j] = (__ldg(bias + c) - __ldg(bnm + c)) * s + __ldg(bnb + c);
    }
#pragma unroll
    for (int i = 0; i < 8; i++) {
        int row = m0 + ty * 8 + i;
        if (row < M) {
            float o[8];
#pragma unroll
            for (int j = 0; j < 8; j++)
                o[j] = fmaxf(fmaf(acc[i][j], sc[j], sh[j]), 0.f);
            float4* op = (float4*)(out + (size_t)row * N + n0 + tx * 8);
            op[0] = make_float4(o[0], o[1], o[2], o[3]);
            op[1] = make_float4(o[4], o[5], o[6], o[7]);
        }
    }
}

// ---------------- head: lin1 + BN + ReLU + lin2 + log_softmax --------------
__global__ void k_head(const float* __restrict__ pooled,
                       const float* __restrict__ lw1, const float* __restrict__ lb1,
                       const float* __restrict__ g3, const float* __restrict__ b3,
                       const float* __restrict__ m3, const float* __restrict__ v3,
                       const float* __restrict__ lw2, const float* __restrict__ lb2,
                       float* __restrict__ out) {
    __shared__ float p[HID];
    __shared__ float h[HID];
    __shared__ float lg[N_OUT];
    __shared__ float red2[2];
    int gph = blockIdx.x;
    int t = threadIdx.x;  // 128 threads

    p[t] = pooled[gph * HID + t];
    __syncthreads();

    float acc = __ldg(lb1 + t);
#pragma unroll 8
    for (int k = 0; k < HID; k++) acc = fmaf(p[k], __ldg(lw1 + k * HID + t), acc);
    float s = __ldg(g3 + t) * rsqrtf(__ldg(v3 + t) + BN_EPS);
    acc = (acc - __ldg(m3 + t)) * s + __ldg(b3 + t);
    h[t] = fmaxf(acc, 0.f);
    __syncthreads();

    if (t < N_OUT) {
        float a = __ldg(lb2 + t);
#pragma unroll 8
        for (int k = 0; k < HID; k++) a = fmaf(h[k], __ldg(lw2 + k * N_OUT + t), a);
        lg[t] = a;
    }
    __syncthreads();

    if (t == 0) {
        float mx = lg[0];
        for (int i = 1; i < N_OUT; i++) mx = fmaxf(mx, lg[i]);
        float se = 0.f;
        for (int i = 0; i < N_OUT; i++) se += expf(lg[i] - mx);
        red2[0] = mx;
        red2[1] = logf(se);
    }
    __syncthreads();

    if (t < N_OUT) out[gph * N_OUT + t] = lg[t] - red2[0] - red2[1];
}

// ---------------- host orchestration --------------------------------------
extern "C" void kernel_launch(void* const* d_in, const int* in_sizes, int n_in,
                              void* d_out, int out_size) {
    const float* x       = (const float*)d_in[0];
    const int*   ei      = (const int*)d_in[1];
    const int*   batch   = (const int*)d_in[2];
    const float* w1      = (const float*)d_in[3];
    const float* b1      = (const float*)d_in[4];
    const float* bn1_g   = (const float*)d_in[5];
    const float* bn1_b   = (const float*)d_in[6];
    const float* bn1_m   = (const float*)d_in[7];
    const float* bn1_v   = (const float*)d_in[8];
    const float* gin_eps = (const float*)d_in[9];
    const float* w2      = (const float*)d_in[10];
    const float* b2      = (const float*)d_in[11];
    const float* bn2_g   = (const float*)d_in[12];
    const float* bn2_b   = (const float*)d_in[13];
    const float* bn2_m   = (const float*)d_in[14];
    const float* bn2_v   = (const float*)d_in[15];
    const float* lin1_w  = (const float*)d_in[16];
    const float* lin1_b  = (const float*)d_in[17];
    const float* bn3_g   = (const float*)d_in[18];
    const float* bn3_b   = (const float*)d_in[19];
    const float* bn3_m   = (const float*)d_in[20];
    const float* bn3_v   = (const float*)d_in[21];
    const float* lin2_w  = (const float*)d_in[22];
    const float* lin2_b  = (const float*)d_in[23];

    float *agg, *h1, *x0, *x1, *pooled;
    cudaGetSymbolAddress((void**)&agg, g_agg);
    cudaGetSymbolAddress((void**)&h1, g_h1);
    cudaGetSymbolAddress((void**)&x0, g_x0);
    cudaGetSymbolAddress((void**)&x1, g_x1);
    cudaGetSymbolAddress((void**)&pooled, g_pooled);

    const int ZT = 256;
    const int agg_n4 = N_NODES * C_IN / 4;
    const int pool_n4 = N_GRAPHS * HID / 4;

    const float* xcur = x;
    float* bufs[2] = {x0, x1};

    for (int l = 0; l < N_LAYERS; l++) {
        k_zero<<<(agg_n4 + ZT - 1) / ZT, ZT>>>((float4*)agg, agg_n4);
        {
            long long th = (long long)N_EDGES * 32;
            int blocks = (int)((th + 255) / 256);
            k_aggregate<<<blocks, 256>>>(xcur, ei, ei + N_EDGES, agg);
        }
        // MLP layer 1: [N_NODES,128] @ [128,256] -> h1, BN1 + ReLU
        {
            dim3 grid((N_NODES + 127) / 128, 2);
            k_gemm_bn_relu<<<grid, 256>>>(
                xcur, agg, gin_eps + l,
                w1 + (size_t)l * C_IN * 2 * HID, b1 + (size_t)l * 2 * HID,
                bn1_g + (size_t)l * 2 * HID, bn1_b + (size_t)l * 2 * HID,
                bn1_m + (size_t)l * 2 * HID, bn1_v + (size_t)l * 2 * HID,
                h1, N_NODES, 2 * HID, C_IN);
        }
        // MLP layer 2: [N_NODES,256] @ [256,128] -> x_next, BN2 + ReLU
        {
            dim3 grid((N_NODES + 127) / 128, 1);
            k_gemm_bn_relu<<<grid, 256>>>(
                h1, nullptr, nullptr,
                w2 + (size_t)l * 2 * HID * HID, b2 + (size_t)l * HID,
                bn2_g + (size_t)l * HID, bn2_b + (size_t)l * HID,
                bn2_m + (size_t)l * HID, bn2_v + (size_t)l * HID,
                bufs[l & 1], N_NODES, HID, 2 * HID);
        }
        xcur = bufs[l & 1];
    }

    k_zero<<<(pool_n4 + ZT - 1) / ZT, ZT>>>((float4*)pooled, pool_n4);
    {
        long long th = (long long)N_NODES * 32;
        int blocks = (int)((th + 255) / 256);
        k_pool<<<blocks, 256>>>(xcur, batch, pooled);
    }
    k_head<<<N_GRAPHS, HID>>>(pooled, lin1_w, lin1_b,
                              bn3_g, bn3_b, bn3_m, bn3_v,
                              lin2_w, lin2_b, (float*)d_out);
}

// round 3
// speedup vs baseline: 1.2802x; 1.2802x over previous
#include <cuda_runtime.h>
#include <cuda_bf16.h>
#include <math.h>
#include <stdint.h>

#define N_NODES 100000
#define N_EDGES 1600000
#define C_IN 128
#define HID 128
#define N_LAYERS 4
#define N_GRAPHS 512
#define N_OUT 10
#define BN_EPS 1e-5f

// ---------------- scratch (static device allocations; no runtime alloc) ----
__device__ float g_agg[(size_t)N_NODES * C_IN];       // 51.2 MB
__device__ float g_h1[(size_t)N_NODES * 2 * HID];     // 102.4 MB
__device__ float g_x0[(size_t)N_NODES * HID];         // 51.2 MB
__device__ float g_x1[(size_t)N_NODES * HID];         // 51.2 MB
__device__ float g_pooled[N_GRAPHS * HID];            // 256 KB
// split+transposed weights in bf16: Wt[n][k]
__device__ __nv_bfloat16 g_w1t_hi[N_LAYERS * 2 * HID * C_IN];
__device__ __nv_bfloat16 g_w1t_lo[N_LAYERS * 2 * HID * C_IN];
__device__ __nv_bfloat16 g_w2t_hi[N_LAYERS * HID * 2 * HID];
__device__ __nv_bfloat16 g_w2t_lo[N_LAYERS * HID * 2 * HID];

// ================= helpers =================
__device__ __forceinline__ uint32_t pack_bf2(float a, float b) {
    __nv_bfloat162 t = __floats2bfloat162_rn(a, b);
    return *reinterpret_cast<uint32_t*>(&t);
}

#define MMA_BF16(c, a, b0, b1)                                               \
    asm volatile("mma.sync.aligned.m16n8k16.row.col.f32.bf16.bf16.f32 "      \
                 "{%0,%1,%2,%3}, {%4,%5,%6,%7}, {%8,%9}, {%0,%1,%2,%3};"     \
                 : "+f"((c)[0]), "+f"((c)[1]), "+f"((c)[2]), "+f"((c)[3])    \
                 : "r"((a)[0]), "r"((a)[1]), "r"((a)[2]), "r"((a)[3]),       \
                   "r"(b0), "r"(b1))

// ---------------- zero ----------------
__global__ void k_zero(float4* __restrict__ p, int n4) {
    int i = blockIdx.x * blockDim.x + threadIdx.x;
    if (i < n4) p[i] = make_float4(0.f, 0.f, 0.f, 0.f);
}

// ---------------- weight prep: transpose + bf16 hi/lo split ----------------
__global__ void k_prep_w(const float* __restrict__ W, __nv_bfloat16* __restrict__ Th,
                         __nv_bfloat16* __restrict__ Tl, int K, int N) {
    int idx = blockIdx.x * blockDim.x + threadIdx.x;
    if (idx >= K * N) return;
    int k = idx / N, n = idx % N;
    float v = W[idx];
    __nv_bfloat16 hi = __float2bfloat16_rn(v);
    float r = v - __bfloat162float(hi);
    Th[(size_t)n * K + k] = hi;
    Tl[(size_t)n * K + k] = __float2bfloat16_rn(r);
}

// ---------------- edge aggregation: agg[dst] += x[src] --------------------
__global__ void k_aggregate(const float* __restrict__ x,
                            const int* __restrict__ src,
                            const int* __restrict__ dst,
                            float* __restrict__ agg) {
    int w = (blockIdx.x * blockDim.x + threadIdx.x) >> 5;
    if (w >= N_EDGES) return;
    int lane = threadIdx.x & 31;
    int s = __ldg(src + w);
    int d = __ldg(dst + w);
    float4 v = ((const float4*)(x + (size_t)s * C_IN))[lane];
    float4* o = ((float4*)(agg + (size_t)d * C_IN)) + lane;
    asm volatile("red.global.add.v4.f32 [%0], {%1,%2,%3,%4};"
                 :: "l"(o), "f"(v.x), "f"(v.y), "f"(v.z), "f"(v.w)
                 : "memory");
}

// ---------------- graph pooling -------------------------------------------
__global__ void k_pool(const float* __restrict__ x,
                       const int* __restrict__ batch,
                       float* __restrict__ pooled) {
    int w = (blockIdx.x * blockDim.x + threadIdx.x) >> 5;
    if (w >= N_NODES) return;
    int lane = threadIdx.x & 31;
    int g = __ldg(batch + w);
    float4 v = ((const float4*)(x + (size_t)w * HID))[lane];
    float4* o = ((float4*)(pooled + (size_t)g * HID)) + lane;
    asm volatile("red.global.add.v4.f32 [%0], {%1,%2,%3,%4};"
                 :: "l"(o), "f"(v.x), "f"(v.y), "f"(v.z), "f"(v.w)
                 : "memory");
}

// ---------------- mma.sync split-bf16 GEMM + bias + BN + ReLU --------------
// out = relu(bn(A' @ Wt^T + bias)); A' = (1+eps)*A + AGG if AGG != null.
// A: [M,K] fp32.  Bth/Btl: [Ntot,K] bf16 (pre-transposed, pre-split).
// Split: D = Ah*Bh + Al*Bh + Ah*Bl (fp32-grade; drops only Al*Bl ~2^-16).
#define BK 32
#define LDT 40                      // bf16 elems per row (8 pad -> conflict-free)
#define TILE_B (128 * LDT * 2)      // 10240 bytes per matrix
#define OFF_AH 0
#define OFF_AL (1 * TILE_B)
#define OFF_BH (2 * TILE_B)
#define OFF_BL (3 * TILE_B)
#define GEMM_SMEM (4 * TILE_B)      // 40960 bytes

__global__ __launch_bounds__(256)
void k_gemm_mma(const float* __restrict__ A,
                const float* __restrict__ AGG,
                const float* __restrict__ epsp,
                const __nv_bfloat16* __restrict__ Bth,
                const __nv_bfloat16* __restrict__ Btl,
                const float* __restrict__ bias,
                const float* __restrict__ bng, const float* __restrict__ bnb,
                const float* __restrict__ bnm, const float* __restrict__ bnv,
                float* __restrict__ out, int M, int Ntot, int K) {
    extern __shared__ __align__(16) char sm[];
    __shared__ float s_sc[128];
    __shared__ float s_sh[128];

    const int tid = threadIdx.x;
    const int wid = tid >> 5;
    const int lane = tid & 31;
    const int warp_m = wid & 3;        // 4 warps over M (32 rows each)
    const int warp_n = wid >> 2;       // 2 warps over N (64 cols each)
    const int g = lane >> 2;           // group row 0..7
    const int q = lane & 3;            // quad col
    const int m0 = blockIdx.x * 128;
    const int n0 = blockIdx.y * 128;

    if (tid < 128) {
        int c = n0 + tid;
        float s = __ldg(bng + c) * rsqrtf(__ldg(bnv + c) + BN_EPS);
        s_sc[tid] = s;
        s_sh[tid] = (__ldg(bias + c) - __ldg(bnm + c)) * s + __ldg(bnb + c);
    }
    const float epsv = (AGG != nullptr) ? (1.0f + __ldg(epsp)) : 0.0f;

    float acc[2][8][4];
#pragma unroll
    for (int mt = 0; mt < 2; mt++)
#pragma unroll
        for (int nt = 0; nt < 8; nt++)
#pragma unroll
            for (int j = 0; j < 4; j++) acc[mt][nt][j] = 0.f;

    const int NCH = K >> 5;  // BK=32 chunks
    for (int c = 0; c < NCH; ++c) {
        const int k0 = c << 5;
        __syncthreads();
        // ---- stage A (fp32 -> bf16 hi/lo) : 128 rows x 32 k ----
#pragma unroll
        for (int i = 0; i < 4; ++i) {
            int idx4 = i * 256 + tid;       // 1024 float4
            int r = idx4 >> 3;              // row 0..127
            int kc = (idx4 & 7) * 4;        // k 0..28
            int row = m0 + r;
            float4 v = make_float4(0.f, 0.f, 0.f, 0.f);
            if (row < M) {
                v = *(const float4*)(A + (size_t)row * K + k0 + kc);
                if (AGG != nullptr) {
                    float4 gg = *(const float4*)(AGG + (size_t)row * K + k0 + kc);
                    v.x = fmaf(v.x, epsv, gg.x);
                    v.y = fmaf(v.y, epsv, gg.y);
                    v.z = fmaf(v.z, epsv, gg.z);
                    v.w = fmaf(v.w, epsv, gg.w);
                }
            }
            float hx = __bfloat162float(__float2bfloat16_rn(v.x));
            float hy = __bfloat162float(__float2bfloat16_rn(v.y));
            float hz = __bfloat162float(__float2bfloat16_rn(v.z));
            float hw = __bfloat162float(__float2bfloat16_rn(v.w));
            uint2 hh = make_uint2(pack_bf2(hx, hy), pack_bf2(hz, hw));
            uint2 ll = make_uint2(pack_bf2(v.x - hx, v.y - hy),
                                  pack_bf2(v.z - hz, v.w - hw));
            uint32_t so = (uint32_t)(r * LDT + kc) * 2;
            *(uint2*)(sm + OFF_AH + so) = hh;
            *(uint2*)(sm + OFF_AL + so) = ll;
        }
        // ---- stage B (bf16 direct copy) : 128 n-rows x 32 k ----
#pragma unroll
        for (int i = 0; i < 2; ++i) {
            int idx = i * 256 + tid;        // 512 x 16B
            int r = idx >> 2;               // n row 0..127
            int kc = (idx & 3) * 8;         // k 0..24
            size_t go = (size_t)(n0 + r) * K + k0 + kc;
            uint4 bh = *(const uint4*)(Bth + go);
            uint4 bl = *(const uint4*)(Btl + go);
            uint32_t so = (uint32_t)(r * LDT + kc) * 2;
            *(uint4*)(sm + OFF_BH + so) = bh;
            *(uint4*)(sm + OFF_BL + so) = bl;
        }
        __syncthreads();

        // ---- compute: 2 k16 steps, 3 products, 16 mma tiles/warp ----
#pragma unroll
        for (int ks = 0; ks < 32; ks += 16) {
            uint32_t ah[2][4], al[2][4];
#pragma unroll
            for (int mt = 0; mt < 2; mt++) {
                uint32_t off = (uint32_t)((warp_m * 32 + mt * 16 + g) * LDT + ks + q * 2) * 2;
                ah[mt][0] = *(uint32_t*)(sm + OFF_AH + off);
                ah[mt][1] = *(uint32_t*)(sm + OFF_AH + off + 8 * LDT * 2);
                ah[mt][2] = *(uint32_t*)(sm + OFF_AH + off + 16);
                ah[mt][3] = *(uint32_t*)(sm + OFF_AH + off + 8 * LDT * 2 + 16);
                al[mt][0] = *(uint32_t*)(sm + OFF_AL + off);
                al[mt][1] = *(uint32_t*)(sm + OFF_AL + off + 8 * LDT * 2);
                al[mt][2] = *(uint32_t*)(sm + OFF_AL + off + 16);
                al[mt][3] = *(uint32_t*)(sm + OFF_AL + off + 8 * LDT * 2 + 16);
            }
#pragma unroll
            for (int nt = 0; nt < 8; nt++) {
                uint32_t boff = (uint32_t)((warp_n * 64 + nt * 8 + g) * LDT + ks + q * 2) * 2;
                uint32_t bh0 = *(uint32_t*)(sm + OFF_BH + boff);
                uint32_t bh1 = *(uint32_t*)(sm + OFF_BH + boff + 16);
                uint32_t bl0 = *(uint32_t*)(sm + OFF_BL + boff);
                uint32_t bl1 = *(uint32_t*)(sm + OFF_BL + boff + 16);
#pragma unroll
                for (int mt = 0; mt < 2; mt++) {
                    MMA_BF16(acc[mt][nt], ah[mt], bh0, bh1);
                    MMA_BF16(acc[mt][nt], al[mt], bh0, bh1);
                    MMA_BF16(acc[mt][nt], ah[mt], bl0, bl1);
                }
            }
        }
    }

    // ---- epilogue: bias+BN+ReLU fused; D frag layout of m16n8 ----
#pragma unroll
    for (int mt = 0; mt < 2; mt++) {
        int r0 = m0 + warp_m * 32 + mt * 16 + g;
        int r1 = r0 + 8;
#pragma unroll
        for (int nt = 0; nt < 8; nt++) {
            int cl = warp_n * 64 + nt * 8 + q * 2;
            float sc0 = s_sc[cl], sc1 = s_sc[cl + 1];
            float sh0 = s_sh[cl], sh1 = s_sh[cl + 1];
            const float* a = acc[mt][nt];
            if (r0 < M) {
                float2 o;
                o.x = fmaxf(fmaf(a[0], sc0, sh0), 0.f);
                o.y = fmaxf(fmaf(a[1], sc1, sh1), 0.f);
                *(float2*)(out + (size_t)r0 * Ntot + n0 + cl) = o;
            }
            if (r1 < M) {
                float2 o;
                o.x = fmaxf(fmaf(a[2], sc0, sh0), 0.f);
                o.y = fmaxf(fmaf(a[3], sc1, sh1), 0.f);
                *(float2*)(out + (size_t)r1 * Ntot + n0 + cl) = o;
            }
        }
    }
}

// ---------------- head ------------------------------------------------------
__global__ void k_head(const float* __restrict__ pooled,
                       const float* __restrict__ lw1, const float* __restrict__ lb1,
                       const float* __restrict__ g3, const float* __restrict__ b3,
                       const float* __restrict__ m3, const float* __restrict__ v3,
                       const float* __restrict__ lw2, const float* __restrict__ lb2,
                       float* __restrict__ out) {
    __shared__ float p[HID];
    __shared__ float h[HID];
    __shared__ float lg[N_OUT];
    __shared__ float red2[2];
    int gph = blockIdx.x;
    int t = threadIdx.x;

    p[t] = pooled[gph * HID + t];
    __syncthreads();

    float acc = __ldg(lb1 + t);
#pragma unroll 8
    for (int k = 0; k < HID; k++) acc = fmaf(p[k], __ldg(lw1 + k * HID + t), acc);
    float s = __ldg(g3 + t) * rsqrtf(__ldg(v3 + t) + BN_EPS);
    acc = (acc - __ldg(m3 + t)) * s + __ldg(b3 + t);
    h[t] = fmaxf(acc, 0.f);
    __syncthreads();

    if (t < N_OUT) {
        float a = __ldg(lb2 + t);
#pragma unroll 8
        for (int k = 0; k < HID; k++) a = fmaf(h[k], __ldg(lw2 + k * N_OUT + t), a);
        lg[t] = a;
    }
    __syncthreads();

    if (t == 0) {
        float mx = lg[0];
        for (int i = 1; i < N_OUT; i++) mx = fmaxf(mx, lg[i]);
        float se = 0.f;
        for (int i = 0; i < N_OUT; i++) se += expf(lg[i] - mx);
        red2[0] = mx;
        red2[1] = logf(se);
    }
    __syncthreads();

    if (t < N_OUT) out[gph * N_OUT + t] = lg[t] - red2[0] - red2[1];
}

// ---------------- host orchestration ----------------------------------------
extern "C" void kernel_launch(void* const* d_in, const int* in_sizes, int n_in,
                              void* d_out, int out_size) {
    const float* x       = (const float*)d_in[0];
    const int*   ei      = (const int*)d_in[1];
    const int*   batch   = (const int*)d_in[2];
    const float* w1      = (const float*)d_in[3];
    const float* b1      = (const float*)d_in[4];
    const float* bn1_g   = (const float*)d_in[5];
    const float* bn1_b   = (const float*)d_in[6];
    const float* bn1_m   = (const float*)d_in[7];
    const float* bn1_v   = (const float*)d_in[8];
    const float* gin_eps = (const float*)d_in[9];
    const float* w2      = (const float*)d_in[10];
    const float* b2      = (const float*)d_in[11];
    const float* bn2_g   = (const float*)d_in[12];
    const float* bn2_b   = (const float*)d_in[13];
    const float* bn2_m   = (const float*)d_in[14];
    const float* bn2_v   = (const float*)d_in[15];
    const float* lin1_w  = (const float*)d_in[16];
    const float* lin1_b  = (const float*)d_in[17];
    const float* bn3_g   = (const float*)d_in[18];
    const float* bn3_b   = (const float*)d_in[19];
    const float* bn3_m   = (const float*)d_in[20];
    const float* bn3_v   = (const float*)d_in[21];
    const float* lin2_w  = (const float*)d_in[22];
    const float* lin2_b  = (const float*)d_in[23];

    float *agg, *h1, *x0, *x1, *pooled;
    __nv_bfloat16 *w1t_hi, *w1t_lo, *w2t_hi, *w2t_lo;
    cudaGetSymbolAddress((void**)&agg, g_agg);
    cudaGetSymbolAddress((void**)&h1, g_h1);
    cudaGetSymbolAddress((void**)&x0, g_x0);
    cudaGetSymbolAddress((void**)&x1, g_x1);
    cudaGetSymbolAddress((void**)&pooled, g_pooled);
    cudaGetSymbolAddress((void**)&w1t_hi, g_w1t_hi);
    cudaGetSymbolAddress((void**)&w1t_lo, g_w1t_lo);
    cudaGetSymbolAddress((void**)&w2t_hi, g_w2t_hi);
    cudaGetSymbolAddress((void**)&w2t_lo, g_w2t_lo);

    const int ZT = 256;
    const int agg_n4 = N_NODES * C_IN / 4;
    const int pool_n4 = N_GRAPHS * HID / 4;
    const int WSZ = C_IN * 2 * HID;  // 32768 elems per layer per matrix

    for (int l = 0; l < N_LAYERS; l++) {
        k_prep_w<<<(WSZ + 255) / 256, 256>>>(w1 + (size_t)l * WSZ,
                                             w1t_hi + (size_t)l * WSZ,
                                             w1t_lo + (size_t)l * WSZ, C_IN, 2 * HID);
        k_prep_w<<<(WSZ + 255) / 256, 256>>>(w2 + (size_t)l * WSZ,
                                             w2t_hi + (size_t)l * WSZ,
                                             w2t_lo + (size_t)l * WSZ, 2 * HID, HID);
    }

    const float* xcur = x;
    float* bufs[2] = {x0, x1};
    const int MT = (N_NODES + 127) / 128;

    for (int l = 0; l < N_LAYERS; l++) {
        k_zero<<<(agg_n4 + ZT - 1) / ZT, ZT>>>((float4*)agg, agg_n4);
        {
            long long th = (long long)N_EDGES * 32;
            int blocks = (int)((th + 255) / 256);
            k_aggregate<<<blocks, 256>>>(xcur, ei, ei + N_EDGES, agg);
        }
        // GEMM1: [100000,128] @ [128,256] (+GIN update) -> h1, BN1 + ReLU
        {
            dim3 grid(MT, 2);
            k_gemm_mma<<<grid, 256, GEMM_SMEM>>>(
                xcur, agg, gin_eps + l,
                w1t_hi + (size_t)l * WSZ, w1t_lo + (size_t)l * WSZ,
                b1 + (size_t)l * 2 * HID,
                bn1_g + (size_t)l * 2 * HID, bn1_b + (size_t)l * 2 * HID,
                bn1_m + (size_t)l * 2 * HID, bn1_v + (size_t)l * 2 * HID,
                h1, N_NODES, 2 * HID, C_IN);
        }
        // GEMM2: [100000,256] @ [256,128] -> x_next, BN2 + ReLU
        {
            dim3 grid(MT, 1);
            k_gemm_mma<<<grid, 256, GEMM_SMEM>>>(
                h1, nullptr, nullptr,
                w2t_hi + (size_t)l * WSZ, w2t_lo + (size_t)l * WSZ,
                b2 + (size_t)l * HID,
                bn2_g + (size_t)l * HID, bn2_b + (size_t)l * HID,
                bn2_m + (size_t)l * HID, bn2_v + (size_t)l * HID,
                bufs[l & 1], N_NODES, HID, 2 * HID);
        }
        xcur = bufs[l & 1];
    }

    k_zero<<<(pool_n4 + ZT - 1) / ZT, ZT>>>((float4*)pooled, pool_n4);
    {
        long long th = (long long)N_NODES * 32;
        int blocks = (int)((th + 255) / 256);
        k_pool<<<blocks, 256>>>(xcur, batch, pooled);
    }
    k_head<<<N_GRAPHS, HID>>>(pooled, lin1_w, lin1_b,
                              bn3_g, bn3_b, bn3_m, bn3_v,
                              lin2_w, lin2_b, (float*)d_out);
}

// round 4
// speedup vs baseline: 2.0905x; 1.6330x over previous
#include <cuda_runtime.h>
#include <cuda_bf16.h>
#include <math.h>
#include <stdint.h>

#define N_NODES 100000
#define N_EDGES 1600000
#define C_IN 128
#define HID 128
#define N_LAYERS 4
#define N_GRAPHS 512
#define N_OUT 10
#define BN_EPS 1e-5f

// ---------------- scratch (static device allocations) ----------------------
__device__ __nv_bfloat16 g_aggh[(size_t)N_NODES * C_IN];   // 25.6 MB
__device__ __nv_bfloat16 g_aggl[(size_t)N_NODES * C_IN];
__device__ __nv_bfloat16 g_h1h[(size_t)N_NODES * 2 * HID]; // 51.2 MB
__device__ __nv_bfloat16 g_h1l[(size_t)N_NODES * 2 * HID];
__device__ __nv_bfloat16 g_xh[(size_t)N_NODES * HID];      // 25.6 MB
__device__ __nv_bfloat16 g_xl[(size_t)N_NODES * HID];
__device__ float g_pooled[N_GRAPHS * HID];
// CSR
__device__ int g_deg[N_NODES];
__device__ int g_rowptr[N_NODES + 1];
__device__ int g_cursor[N_NODES];
__device__ int g_bsum[128];
__device__ int g_csrsrc[N_EDGES];
// split+transposed weights in bf16: Wt[n][k]
__device__ __nv_bfloat16 g_w1t_hi[N_LAYERS * 2 * HID * C_IN];
__device__ __nv_bfloat16 g_w1t_lo[N_LAYERS * 2 * HID * C_IN];
__device__ __nv_bfloat16 g_w2t_hi[N_LAYERS * HID * 2 * HID];
__device__ __nv_bfloat16 g_w2t_lo[N_LAYERS * HID * 2 * HID];

// ================= helpers =================
__device__ __forceinline__ uint32_t smem_u32(const void* p) {
    uint32_t a;
    asm("{ .reg .u64 t; cvta.to.shared.u64 t, %1; cvt.u32.u64 %0, t; }"
        : "=r"(a) : "l"(p));
    return a;
}

__device__ __forceinline__ uint32_t pack_bf2(float a, float b) {
    __nv_bfloat162 t = __floats2bfloat162_rn(a, b);
    return *reinterpret_cast<uint32_t*>(&t);
}

__device__ __forceinline__ float2 unpk(uint32_t u) {
    __nv_bfloat162 t = *reinterpret_cast<__nv_bfloat162*>(&u);
    return __bfloat1622float2(t);
}

#define MMA_BF16(c, a, b0, b1)                                               \
    asm volatile("mma.sync.aligned.m16n8k16.row.col.f32.bf16.bf16.f32 "      \
                 "{%0,%1,%2,%3}, {%4,%5,%6,%7}, {%8,%9}, {%0,%1,%2,%3};"     \
                 : "+f"((c)[0]), "+f"((c)[1]), "+f"((c)[2]), "+f"((c)[3])    \
                 : "r"((a)[0]), "r"((a)[1]), "r"((a)[2]), "r"((a)[3]),       \
                   "r"(b0), "r"(b1))

__device__ __forceinline__ void cp16(uint32_t dst, const void* src, uint32_t sz) {
    asm volatile("cp.async.cg.shared.global [%0], [%1], 16, %2;"
                 :: "r"(dst), "l"(src), "r"(sz) : "memory");
}
#define CP_COMMIT() asm volatile("cp.async.commit_group;" ::: "memory")
#define CP_WAIT(n)  asm volatile("cp.async.wait_group %0;" :: "n"(n) : "memory")

// ---------------- small utility kernels ------------------------------------
__global__ void k_zero_f4(float4* __restrict__ p, int n4) {
    int i = blockIdx.x * blockDim.x + threadIdx.x;
    if (i < n4) p[i] = make_float4(0.f, 0.f, 0.f, 0.f);
}
__global__ void k_zero_i(int* __restrict__ p, int n) {
    int i = blockIdx.x * blockDim.x + threadIdx.x;
    if (i < n) p[i] = 0;
}

// ---------------- CSR build -------------------------------------------------
__global__ void k_hist(const int* __restrict__ dst, int* __restrict__ deg) {
    int e = blockIdx.x * blockDim.x + threadIdx.x;
    if (e < N_EDGES) atomicAdd(&deg[dst[e]], 1);
}
__global__ void k_scan_block(const int* __restrict__ deg, int* __restrict__ rowptr,
                             int* __restrict__ bsum) {
    __shared__ int s[1024];
    int gid = blockIdx.x * 1024 + threadIdx.x;
    int v = (gid < N_NODES) ? deg[gid] : 0;
    s[threadIdx.x] = v;
    __syncthreads();
#pragma unroll
    for (int off = 1; off < 1024; off <<= 1) {
        int t = (threadIdx.x >= off) ? s[threadIdx.x - off] : 0;
        __syncthreads();
        s[threadIdx.x] += t;
        __syncthreads();
    }
    if (gid < N_NODES) rowptr[gid] = s[threadIdx.x] - v;  // exclusive
    if (threadIdx.x == 1023) bsum[blockIdx.x] = s[1023];
}
__global__ void k_scan_sums(int* __restrict__ bsum, int nb) {
    if (threadIdx.x == 0) {
        int run = 0;
        for (int i = 0; i < nb; i++) { int t = bsum[i]; bsum[i] = run; run += t; }
    }
}
__global__ void k_scan_add(int* __restrict__ rowptr, const int* __restrict__ bsum,
                           int* __restrict__ cursor) {
    int gid = blockIdx.x * blockDim.x + threadIdx.x;
    if (gid < N_NODES) {
        int v = rowptr[gid] + bsum[gid >> 10];
        rowptr[gid] = v;
        cursor[gid] = v;
    }
    if (gid == 0) rowptr[N_NODES] = N_EDGES;
}
__global__ void k_scatter(const int* __restrict__ src, const int* __restrict__ dst,
                          int* __restrict__ cursor, int* __restrict__ csrsrc) {
    int e = blockIdx.x * blockDim.x + threadIdx.x;
    if (e < N_EDGES) {
        int pos = atomicAdd(&cursor[dst[e]], 1);
        csrsrc[pos] = src[e];
    }
}

// ---------------- weight prep: transpose + bf16 hi/lo split ----------------
// W layouts are [L][K][N]; output Wt [L][N][K]. blockIdx.y = layer.
__global__ void k_prep_w(const float* __restrict__ W, __nv_bfloat16* __restrict__ Th,
                         __nv_bfloat16* __restrict__ Tl, int K, int N) {
    int idx = blockIdx.x * blockDim.x + threadIdx.x;
    if (idx >= K * N) return;
    size_t lofs = (size_t)blockIdx.y * K * N;
    int k = idx / N, n = idx % N;
    float v = W[lofs + idx];
    __nv_bfloat16 hi = __float2bfloat16_rn(v);
    float r = v - __bfloat162float(hi);
    Th[lofs + (size_t)n * K + k] = hi;
    Tl[lofs + (size_t)n * K + k] = __float2bfloat16_rn(r);
}

// ---------------- gather aggregation (layer 0: fp32 input) -----------------
// agg[n] = (1+eps)*x[n] + sum_{e in csr[n]} x[src_e]; output split bf16.
__global__ void k_gather_first(const float* __restrict__ x,
                               const int* __restrict__ rowptr,
                               const int* __restrict__ csrsrc,
                               const float* __restrict__ epsp,
                               __nv_bfloat16* __restrict__ oh,
                               __nv_bfloat16* __restrict__ ol) {
    int n = (blockIdx.x * blockDim.x + threadIdx.x) >> 5;
    if (n >= N_NODES) return;
    int lane = threadIdx.x & 31;
    float epsv = 1.0f + __ldg(epsp);
    float4 v = *(const float4*)(x + (size_t)n * C_IN + lane * 4);
    float4 acc;
    acc.x = epsv * v.x; acc.y = epsv * v.y; acc.z = epsv * v.z; acc.w = epsv * v.w;
    int beg = __ldg(rowptr + n), end = __ldg(rowptr + n + 1);
    int e = beg;
    for (; e + 1 < end; e += 2) {
        int s0 = __ldg(csrsrc + e), s1 = __ldg(csrsrc + e + 1);
        float4 a = *(const float4*)(x + (size_t)s0 * C_IN + lane * 4);
        float4 b = *(const float4*)(x + (size_t)s1 * C_IN + lane * 4);
        acc.x += a.x + b.x; acc.y += a.y + b.y;
        acc.z += a.z + b.z; acc.w += a.w + b.w;
    }
    if (e < end) {
        int s0 = __ldg(csrsrc + e);
        float4 a = *(const float4*)(x + (size_t)s0 * C_IN + lane * 4);
        acc.x += a.x; acc.y += a.y; acc.z += a.z; acc.w += a.w;
    }
    float hx = __bfloat162float(__float2bfloat16_rn(acc.x));
    float hy = __bfloat162float(__float2bfloat16_rn(acc.y));
    float hz = __bfloat162float(__float2bfloat16_rn(acc.z));
    float hw = __bfloat162float(__float2bfloat16_rn(acc.w));
    size_t o = (size_t)n * C_IN + lane * 4;
    *(uint2*)(oh + o) = make_uint2(pack_bf2(hx, hy), pack_bf2(hz, hw));
    *(uint2*)(ol + o) = make_uint2(pack_bf2(acc.x - hx, acc.y - hy),
                                   pack_bf2(acc.z - hz, acc.w - hw));
}

// ---------------- gather aggregation (layers 1..3: split bf16 input) -------
__global__ void k_gather_next(const __nv_bfloat16* __restrict__ xh,
                              const __nv_bfloat16* __restrict__ xl,
                              const int* __restrict__ rowptr,
                              const int* __restrict__ csrsrc,
                              const float* __restrict__ epsp,
                              __nv_bfloat16* __restrict__ oh,
                              __nv_bfloat16* __restrict__ ol) {
    int n = (blockIdx.x * blockDim.x + threadIdx.x) >> 5;
    if (n >= N_NODES) return;
    int lane = threadIdx.x & 31;
    float epsv = 1.0f + __ldg(epsp);
    size_t self = (size_t)n * HID + lane * 4;
    uint2 uh = *(const uint2*)(xh + self);
    uint2 ul = *(const uint2*)(xl + self);
    float2 h0 = unpk(uh.x), h1 = unpk(uh.y), l0 = unpk(ul.x), l1 = unpk(ul.y);
    float4 acc;
    acc.x = epsv * (h0.x + l0.x); acc.y = epsv * (h0.y + l0.y);
    acc.z = epsv * (h1.x + l1.x); acc.w = epsv * (h1.y + l1.y);
    int beg = __ldg(rowptr + n), end = __ldg(rowptr + n + 1);
    int e = beg;
    for (; e + 1 < end; e += 2) {
        int s0 = __ldg(csrsrc + e), s1 = __ldg(csrsrc + e + 1);
        size_t o0 = (size_t)s0 * HID + lane * 4;
        size_t o1 = (size_t)s1 * HID + lane * 4;
        uint2 ah = *(const uint2*)(xh + o0), al = *(const uint2*)(xl + o0);
        uint2 bh = *(const uint2*)(xh + o1), bl = *(const uint2*)(xl + o1);
        float2 p0 = unpk(ah.x), p1 = unpk(ah.y), p2 = unpk(al.x), p3 = unpk(al.y);
        float2 q0 = unpk(bh.x), q1 = unpk(bh.y), q2 = unpk(bl.x), q3 = unpk(bl.y);
        acc.x += p0.x + p2.x + q0.x + q2.x;
        acc.y += p0.y + p2.y + q0.y + q2.y;
        acc.z += p1.x + p3.x + q1.x + q3.x;
        acc.w += p1.y + p3.y + q1.y + q3.y;
    }
    if (e < end) {
        int s0 = __ldg(csrsrc + e);
        size_t o0 = (size_t)s0 * HID + lane * 4;
        uint2 ah = *(const uint2*)(xh + o0), al = *(const uint2*)(xl + o0);
        float2 p0 = unpk(ah.x), p1 = unpk(ah.y), p2 = unpk(al.x), p3 = unpk(al.y);
        acc.x += p0.x + p2.x; acc.y += p0.y + p2.y;
        acc.z += p1.x + p3.x; acc.w += p1.y + p3.y;
    }
    float hx = __bfloat162float(__float2bfloat16_rn(acc.x));
    float hy = __bfloat162float(__float2bfloat16_rn(acc.y));
    float hz = __bfloat162float(__float2bfloat16_rn(acc.z));
    float hw = __bfloat162float(__float2bfloat16_rn(acc.w));
    size_t o = (size_t)n * C_IN + lane * 4;
    *(uint2*)(oh + o) = make_uint2(pack_bf2(hx, hy), pack_bf2(hz, hw));
    *(uint2*)(ol + o) = make_uint2(pack_bf2(acc.x - hx, acc.y - hy),
                                   pack_bf2(acc.z - hz, acc.w - hw));
}

// ---------------- cp.async double-buffered split-bf16 GEMM ------------------
// out = relu(bn(A @ Wt^T + bias)), A = Ah+Al [M,K] bf16, Wt = Bh+Bl [Ntot,K].
// D = Ah*Bh + Al*Bh + Ah*Bl. Output split back to bf16 hi/lo.
#define LDT 40
#define TILE_B (128 * LDT * 2)        // 10240 B per matrix
#define OFF_AH 0
#define OFF_AL (1 * TILE_B)
#define OFF_BH (2 * TILE_B)
#define OFF_BL (3 * TILE_B)
#define STG (4 * TILE_B)              // 40960 B per stage
#define GEMM_SMEM (2 * STG)           // 81920 B

__global__ __launch_bounds__(256)
void k_gemm_mma(const __nv_bfloat16* __restrict__ Ah,
                const __nv_bfloat16* __restrict__ Al,
                const __nv_bfloat16* __restrict__ Bh,
                const __nv_bfloat16* __restrict__ Bl,
                const float* __restrict__ bias,
                const float* __restrict__ bng, const float* __restrict__ bnb,
                const float* __restrict__ bnm, const float* __restrict__ bnv,
                __nv_bfloat16* __restrict__ outh, __nv_bfloat16* __restrict__ outl,
                int M, int Ntot, int K) {
    extern __shared__ __align__(16) char sm[];
    __shared__ float s_sc[128];
    __shared__ float s_sh[128];

    const int tid = threadIdx.x;
    const int wid = tid >> 5;
    const int lane = tid & 31;
    const int warp_m = wid & 3;
    const int warp_n = wid >> 2;
    const int g = lane >> 2;
    const int q = lane & 3;
    const int m0 = blockIdx.x * 128;
    const int n0 = blockIdx.y * 128;
    const uint32_t smb = smem_u32(sm);

    if (tid < 128) {
        int c = n0 + tid;
        float s = __ldg(bng + c) * rsqrtf(__ldg(bnv + c) + BN_EPS);
        s_sc[tid] = s;
        s_sh[tid] = (__ldg(bias + c) - __ldg(bnm + c)) * s + __ldg(bnb + c);
    }

    float acc[2][8][4];
#pragma unroll
    for (int mt = 0; mt < 2; mt++)
#pragma unroll
        for (int nt = 0; nt < 8; nt++)
#pragma unroll
            for (int j = 0; j < 4; j++) acc[mt][nt][j] = 0.f;

    const int NCH = K >> 5;

    // prefetch helper (inlined by macro-like lambda)
    auto prefetch = [&](int c) {
        const uint32_t base = smb + (c & 1) * STG;
        const int k0 = c << 5;
#pragma unroll
        for (int i = 0; i < 2; ++i) {
            int idx = i * 256 + tid;       // 512 chunks of 16B per matrix
            int r = idx >> 2;              // 0..127
            int kc = (idx & 3) * 8;        // 0,8,16,24
            uint32_t so = (uint32_t)(r * LDT + kc) * 2;
            int row = m0 + r;
            uint32_t sz = (row < M) ? 16u : 0u;
            size_t ga = (size_t)row * K + k0 + kc;
            cp16(base + OFF_AH + so, Ah + ga, sz);
            cp16(base + OFF_AL + so, Al + ga, sz);
            size_t gb = (size_t)(n0 + r) * K + k0 + kc;
            cp16(base + OFF_BH + so, Bh + gb, 16u);
            cp16(base + OFF_BL + so, Bl + gb, 16u);
        }
    };

    prefetch(0);
    CP_COMMIT();

    for (int c = 0; c < NCH; ++c) {
        if (c + 1 < NCH) {
            prefetch(c + 1);
            CP_COMMIT();
            CP_WAIT(1);
        } else {
            CP_WAIT(0);
        }
        __syncthreads();
        const char* sb = sm + (c & 1) * STG;
#pragma unroll
        for (int ks = 0; ks < 32; ks += 16) {
            uint32_t ah[2][4], al[2][4];
#pragma unroll
            for (int mt = 0; mt < 2; mt++) {
                uint32_t off = (uint32_t)((warp_m * 32 + mt * 16 + g) * LDT + ks + q * 2) * 2;
                ah[mt][0] = *(const uint32_t*)(sb + OFF_AH + off);
                ah[mt][1] = *(const uint32_t*)(sb + OFF_AH + off + 8 * LDT * 2);
                ah[mt][2] = *(const uint32_t*)(sb + OFF_AH + off + 16);
                ah[mt][3] = *(const uint32_t*)(sb + OFF_AH + off + 8 * LDT * 2 + 16);
                al[mt][0] = *(const uint32_t*)(sb + OFF_AL + off);
                al[mt][1] = *(const uint32_t*)(sb + OFF_AL + off + 8 * LDT * 2);
                al[mt][2] = *(const uint32_t*)(sb + OFF_AL + off + 16);
                al[mt][3] = *(const uint32_t*)(sb + OFF_AL + off + 8 * LDT * 2 + 16);
            }
#pragma unroll
            for (int nt = 0; nt < 8; nt++) {
                uint32_t boff = (uint32_t)((warp_n * 64 + nt * 8 + g) * LDT + ks + q * 2) * 2;
                uint32_t bh0 = *(const uint32_t*)(sb + OFF_BH + boff);
                uint32_t bh1 = *(const uint32_t*)(sb + OFF_BH + boff + 16);
                uint32_t bl0 = *(const uint32_t*)(sb + OFF_BL + boff);
                uint32_t bl1 = *(const uint32_t*)(sb + OFF_BL + boff + 16);
#pragma unroll
                for (int mt = 0; mt < 2; mt++) {
                    MMA_BF16(acc[mt][nt], ah[mt], bh0, bh1);
                    MMA_BF16(acc[mt][nt], al[mt], bh0, bh1);
                    MMA_BF16(acc[mt][nt], ah[mt], bl0, bl1);
                }
            }
        }
        __syncthreads();
    }

    // ---- epilogue: bias+BN+ReLU, split to bf16 hi/lo ----
#pragma unroll
    for (int mt = 0; mt < 2; mt++) {
        int r0 = m0 + warp_m * 32 + mt * 16 + g;
        int r1 = r0 + 8;
#pragma unroll
        for (int nt = 0; nt < 8; nt++) {
            int cl = warp_n * 64 + nt * 8 + q * 2;
            float sc0 = s_sc[cl], sc1 = s_sc[cl + 1];
            float sh0 = s_sh[cl], sh1 = s_sh[cl + 1];
            const float* a = acc[mt][nt];
            if (r0 < M) {
                float o0 = fmaxf(fmaf(a[0], sc0, sh0), 0.f);
                float o1 = fmaxf(fmaf(a[1], sc1, sh1), 0.f);
                float h0 = __bfloat162float(__float2bfloat16_rn(o0));
                float h1 = __bfloat162float(__float2bfloat16_rn(o1));
                size_t o = (size_t)r0 * Ntot + n0 + cl;
                *(uint32_t*)(outh + o) = pack_bf2(h0, h1);
                *(uint32_t*)(outl + o) = pack_bf2(o0 - h0, o1 - h1);
            }
            if (r1 < M) {
                float o0 = fmaxf(fmaf(a[2], sc0, sh0), 0.f);
                float o1 = fmaxf(fmaf(a[3], sc1, sh1), 0.f);
                float h0 = __bfloat162float(__float2bfloat16_rn(o0));
                float h1 = __bfloat162float(__float2bfloat16_rn(o1));
                size_t o = (size_t)r1 * Ntot + n0 + cl;
                *(uint32_t*)(outh + o) = pack_bf2(h0, h1);
                *(uint32_t*)(outl + o) = pack_bf2(o0 - h0, o1 - h1);
            }
        }
    }
}

// ---------------- graph pooling (reads split bf16 x) ------------------------
__global__ void k_pool(const __nv_bfloat16* __restrict__ xh,
                       const __nv_bfloat16* __restrict__ xl,
                       const int* __restrict__ batch,
                       float* __restrict__ pooled) {
    int n = (blockIdx.x * blockDim.x + threadIdx.x) >> 5;
    if (n >= N_NODES) return;
    int lane = threadIdx.x & 31;
    size_t o = (size_t)n * HID + lane * 4;
    uint2 uh = *(const uint2*)(xh + o);
    uint2 ul = *(const uint2*)(xl + o);
    float2 h0 = unpk(uh.x), h1 = unpk(uh.y), l0 = unpk(ul.x), l1 = unpk(ul.y);
    int gph = __ldg(batch + n);
    float* op = pooled + (size_t)gph * HID + lane * 4;
    asm volatile("red.global.add.v4.f32 [%0], {%1,%2,%3,%4};"
                 :: "l"(op), "f"(h0.x + l0.x), "f"(h0.y + l0.y),
                    "f"(h1.x + l1.x), "f"(h1.y + l1.y)
                 : "memory");
}

// ---------------- head ------------------------------------------------------
__global__ void k_head(const float* __restrict__ pooled,
                       const float* __restrict__ lw1, const float* __restrict__ lb1,
                       const float* __restrict__ g3, const float* __restrict__ b3,
                       const float* __restrict__ m3, const float* __restrict__ v3,
                       const float* __restrict__ lw2, const float* __restrict__ lb2,
                       float* __restrict__ out) {
    __shared__ float p[HID];
    __shared__ float h[HID];
    __shared__ float lg[N_OUT];
    __shared__ float red2[2];
    int gph = blockIdx.x;
    int t = threadIdx.x;

    p[t] = pooled[gph * HID + t];
    __syncthreads();

    float acc = __ldg(lb1 + t);
#pragma unroll 8
    for (int k = 0; k < HID; k++) acc = fmaf(p[k], __ldg(lw1 + k * HID + t), acc);
    float s = __ldg(g3 + t) * rsqrtf(__ldg(v3 + t) + BN_EPS);
    acc = (acc - __ldg(m3 + t)) * s + __ldg(b3 + t);
    h[t] = fmaxf(acc, 0.f);
    __syncthreads();

    if (t < N_OUT) {
        float a = __ldg(lb2 + t);
#pragma unroll 8
        for (int k = 0; k < HID; k++) a = fmaf(h[k], __ldg(lw2 + k * N_OUT + t), a);
        lg[t] = a;
    }
    __syncthreads();

    if (t == 0) {
        float mx = lg[0];
        for (int i = 1; i < N_OUT; i++) mx = fmaxf(mx, lg[i]);
        float se = 0.f;
        for (int i = 0; i < N_OUT; i++) se += expf(lg[i] - mx);
        red2[0] = mx;
        red2[1] = logf(se);
    }
    __syncthreads();

    if (t < N_OUT) out[gph * N_OUT + t] = lg[t] - red2[0] - red2[1];
}

// ---------------- host orchestration ----------------------------------------
extern "C" void kernel_launch(void* const* d_in, const int* in_sizes, int n_in,
                              void* d_out, int out_size) {
    const float* x       = (const float*)d_in[0];
    const int*   ei      = (const int*)d_in[1];
    const int*   batch   = (const int*)d_in[2];
    const float* w1      = (const float*)d_in[3];
    const float* b1      = (const float*)d_in[4];
    const float* bn1_g   = (const float*)d_in[5];
    const float* bn1_b   = (const float*)d_in[6];
    const float* bn1_m   = (const float*)d_in[7];
    const float* bn1_v   = (const float*)d_in[8];
    const float* gin_eps = (const float*)d_in[9];
    const float* w2      = (const float*)d_in[10];
    const float* b2      = (const float*)d_in[11];
    const float* bn2_g   = (const float*)d_in[12];
    const float* bn2_b   = (const float*)d_in[13];
    const float* bn2_m   = (const float*)d_in[14];
    const float* bn2_v   = (const float*)d_in[15];
    const float* lin1_w  = (const float*)d_in[16];
    const float* lin1_b  = (const float*)d_in[17];
    const float* bn3_g   = (const float*)d_in[18];
    const float* bn3_b   = (const float*)d_in[19];
    const float* bn3_m   = (const float*)d_in[20];
    const float* bn3_v   = (const float*)d_in[21];
    const float* lin2_w  = (const float*)d_in[22];
    const float* lin2_b  = (const float*)d_in[23];

    __nv_bfloat16 *aggh, *aggl, *h1h, *h1l, *xh, *xl;
    __nv_bfloat16 *w1t_hi, *w1t_lo, *w2t_hi, *w2t_lo;
    float* pooled;
    int *deg, *rowptr, *cursor, *bsum, *csrsrc;
    cudaGetSymbolAddress((void**)&aggh, g_aggh);
    cudaGetSymbolAddress((void**)&aggl, g_aggl);
    cudaGetSymbolAddress((void**)&h1h, g_h1h);
    cudaGetSymbolAddress((void**)&h1l, g_h1l);
    cudaGetSymbolAddress((void**)&xh, g_xh);
    cudaGetSymbolAddress((void**)&xl, g_xl);
    cudaGetSymbolAddress((void**)&pooled, g_pooled);
    cudaGetSymbolAddress((void**)&deg, g_deg);
    cudaGetSymbolAddress((void**)&rowptr, g_rowptr);
    cudaGetSymbolAddress((void**)&cursor, g_cursor);
    cudaGetSymbolAddress((void**)&bsum, g_bsum);
    cudaGetSymbolAddress((void**)&csrsrc, g_csrsrc);
    cudaGetSymbolAddress((void**)&w1t_hi, g_w1t_hi);
    cudaGetSymbolAddress((void**)&w1t_lo, g_w1t_lo);
    cudaGetSymbolAddress((void**)&w2t_hi, g_w2t_hi);
    cudaGetSymbolAddress((void**)&w2t_lo, g_w2t_lo);

    cudaFuncSetAttribute(k_gemm_mma, cudaFuncAttributeMaxDynamicSharedMemorySize,
                         GEMM_SMEM);

    const int WSZ = C_IN * 2 * HID;  // 32768 per layer per matrix
    const int NB = (N_NODES + 1023) / 1024;

    // --- weight prep (all layers in one launch each) ---
    {
        dim3 gr((WSZ + 255) / 256, N_LAYERS);
        k_prep_w<<<gr, 256>>>(w1, w1t_hi, w1t_lo, C_IN, 2 * HID);
        k_prep_w<<<gr, 256>>>(w2, w2t_hi, w2t_lo, 2 * HID, HID);
    }

    // --- CSR build ---
    k_zero_i<<<(N_NODES + 255) / 256, 256>>>(deg, N_NODES);
    k_hist<<<(N_EDGES + 255) / 256, 256>>>(ei + N_EDGES, deg);
    k_scan_block<<<NB, 1024>>>(deg, rowptr, bsum);
    k_scan_sums<<<1, 32>>>(bsum, NB);
    k_scan_add<<<(N_NODES + 255) / 256, 256>>>(rowptr, bsum, cursor);
    k_scatter<<<(N_EDGES + 255) / 256, 256>>>(ei, ei + N_EDGES, cursor, csrsrc);

    const int MT = (N_NODES + 127) / 128;
    const int GB = (N_NODES * 32 + 255) / 256;  // gather/pool blocks

    for (int l = 0; l < N_LAYERS; l++) {
        if (l == 0)
            k_gather_first<<<GB, 256>>>(x, rowptr, csrsrc, gin_eps + l, aggh, aggl);
        else
            k_gather_next<<<GB, 256>>>(xh, xl, rowptr, csrsrc, gin_eps + l, aggh, aggl);
        // GEMM1: [100000,128]@[128,256] -> h1 (split bf16), BN1+ReLU
        {
            dim3 grid(MT, 2);
            k_gemm_mma<<<grid, 256, GEMM_SMEM>>>(
                aggh, aggl,
                w1t_hi + (size_t)l * WSZ, w1t_lo + (size_t)l * WSZ,
                b1 + (size_t)l * 2 * HID,
                bn1_g + (size_t)l * 2 * HID, bn1_b + (size_t)l * 2 * HID,
                bn1_m + (size_t)l * 2 * HID, bn1_v + (size_t)l * 2 * HID,
                h1h, h1l, N_NODES, 2 * HID, C_IN);
        }
        // GEMM2: [100000,256]@[256,128] -> x (split bf16), BN2+ReLU
        {
            dim3 grid(MT, 1);
            k_gemm_mma<<<grid, 256, GEMM_SMEM>>>(
                h1h, h1l,
                w2t_hi + (size_t)l * WSZ, w2t_lo + (size_t)l * WSZ,
                b2 + (size_t)l * HID,
                bn2_g + (size_t)l * HID, bn2_b + (size_t)l * HID,
                bn2_m + (size_t)l * HID, bn2_v + (size_t)l * HID,
                xh, xl, N_NODES, HID, 2 * HID);
        }
    }

    k_zero_f4<<<(N_GRAPHS * HID / 4 + 255) / 256, 256>>>((float4*)pooled,
                                                         N_GRAPHS * HID / 4);
    k_pool<<<GB, 256>>>(xh, xl, batch, pooled);
    k_head<<<N_GRAPHS, HID>>>(pooled, lin1_w, lin1_b,
                              bn3_g, bn3_b, bn3_m, bn3_v,
                              lin2_w, lin2_b, (float*)d_out);
}

// round 5
// speedup vs baseline: 2.4780x; 1.1853x over previous
#include <cuda_runtime.h>
#include <cuda_bf16.h>
#include <math.h>
#include <stdint.h>

#define N_NODES 100000
#define N_EDGES 1600000
#define C_IN 128
#define HID 128
#define N_LAYERS 4
#define N_GRAPHS 512
#define N_OUT 10
#define BN_EPS 1e-5f

// ---------------- scratch (static device allocations) ----------------------
__device__ __nv_bfloat16 g_aggh[(size_t)N_NODES * C_IN];   // planar (GEMM1 A)
__device__ __nv_bfloat16 g_aggl[(size_t)N_NODES * C_IN];
__device__ __nv_bfloat16 g_h1h[(size_t)N_NODES * 2 * HID]; // planar (GEMM2 A)
__device__ __nv_bfloat16 g_h1l[(size_t)N_NODES * 2 * HID];
__device__ __nv_bfloat16 g_xp[(size_t)N_NODES * 2 * HID];  // packed hi|lo x (51.2MB)
__device__ float g_pooled[N_GRAPHS * HID];
// CSR
__device__ int g_deg[N_NODES];
__device__ int g_rowptr[N_NODES + 1];
__device__ int g_cursor[N_NODES];
__device__ int g_bsum[128];
__device__ int g_csrsrc[N_EDGES];
// split+transposed weights in bf16: Wt[n][k]
__device__ __nv_bfloat16 g_w1t_hi[N_LAYERS * 2 * HID * C_IN];
__device__ __nv_bfloat16 g_w1t_lo[N_LAYERS * 2 * HID * C_IN];
__device__ __nv_bfloat16 g_w2t_hi[N_LAYERS * HID * 2 * HID];
__device__ __nv_bfloat16 g_w2t_lo[N_LAYERS * HID * 2 * HID];

// ================= helpers =================
__device__ __forceinline__ uint32_t smem_u32(const void* p) {
    uint32_t a;
    asm("{ .reg .u64 t; cvta.to.shared.u64 t, %1; cvt.u32.u64 %0, t; }"
        : "=r"(a) : "l"(p));
    return a;
}
__device__ __forceinline__ uint32_t pack_bf2(float a, float b) {
    __nv_bfloat162 t = __floats2bfloat162_rn(a, b);
    return *reinterpret_cast<uint32_t*>(&t);
}
__device__ __forceinline__ float2 unpk(uint32_t u) {
    __nv_bfloat162 t = *reinterpret_cast<__nv_bfloat162*>(&u);
    return __bfloat1622float2(t);
}

#define MMA_BF16(c, a, b0, b1)                                               \
    asm volatile("mma.sync.aligned.m16n8k16.row.col.f32.bf16.bf16.f32 "      \
                 "{%0,%1,%2,%3}, {%4,%5,%6,%7}, {%8,%9}, {%0,%1,%2,%3};"     \
                 : "+f"((c)[0]), "+f"((c)[1]), "+f"((c)[2]), "+f"((c)[3])    \
                 : "r"((a)[0]), "r"((a)[1]), "r"((a)[2]), "r"((a)[3]),       \
                   "r"(b0), "r"(b1))

#define LDSM_X4(R, addr)                                                     \
    asm volatile("ldmatrix.sync.aligned.m8n8.x4.shared.b16 "                 \
                 "{%0,%1,%2,%3}, [%4];"                                      \
                 : "=r"((R)[0]), "=r"((R)[1]), "=r"((R)[2]), "=r"((R)[3])    \
                 : "r"(addr))

__device__ __forceinline__ void cp16(uint32_t dst, const void* src, uint32_t sz) {
    asm volatile("cp.async.cg.shared.global [%0], [%1], 16, %2;"
                 :: "r"(dst), "l"(src), "r"(sz) : "memory");
}
#define CP_COMMIT() asm volatile("cp.async.commit_group;" ::: "memory")
#define CP_WAIT(n)  asm volatile("cp.async.wait_group %0;" :: "n"(n) : "memory")

// ---------------- small utility kernels ------------------------------------
__global__ void k_zero_f4(float4* __restrict__ p, int n4) {
    int i = blockIdx.x * blockDim.x + threadIdx.x;
    if (i < n4) p[i] = make_float4(0.f, 0.f, 0.f, 0.f);
}
__global__ void k_zero_i(int* __restrict__ p, int n) {
    int i = blockIdx.x * blockDim.x + threadIdx.x;
    if (i < n) p[i] = 0;
}

// ---------------- CSR build -------------------------------------------------
__global__ void k_hist(const int* __restrict__ dst, int* __restrict__ deg) {
    int e = blockIdx.x * blockDim.x + threadIdx.x;
    if (e < N_EDGES) atomicAdd(&deg[dst[e]], 1);
}
__global__ void k_scan_block(const int* __restrict__ deg, int* __restrict__ rowptr,
                             int* __restrict__ bsum) {
    __shared__ int s[1024];
    int gid = blockIdx.x * 1024 + threadIdx.x;
    int v = (gid < N_NODES) ? deg[gid] : 0;
    s[threadIdx.x] = v;
    __syncthreads();
#pragma unroll
    for (int off = 1; off < 1024; off <<= 1) {
        int t = (threadIdx.x >= off) ? s[threadIdx.x - off] : 0;
        __syncthreads();
        s[threadIdx.x] += t;
        __syncthreads();
    }
    if (gid < N_NODES) rowptr[gid] = s[threadIdx.x] - v;
    if (threadIdx.x == 1023) bsum[blockIdx.x] = s[1023];
}
__global__ void k_scan_sums(int* __restrict__ bsum, int nb) {
    if (threadIdx.x == 0) {
        int run = 0;
        for (int i = 0; i < nb; i++) { int t = bsum[i]; bsum[i] = run; run += t; }
    }
}
__global__ void k_scan_add(int* __restrict__ rowptr, const int* __restrict__ bsum,
                           int* __restrict__ cursor) {
    int gid = blockIdx.x * blockDim.x + threadIdx.x;
    if (gid < N_NODES) {
        int v = rowptr[gid] + bsum[gid >> 10];
        rowptr[gid] = v;
        cursor[gid] = v;
    }
    if (gid == 0) rowptr[N_NODES] = N_EDGES;
}
__global__ void k_scatter(const int* __restrict__ src, const int* __restrict__ dst,
                          int* __restrict__ cursor, int* __restrict__ csrsrc) {
    int e = blockIdx.x * blockDim.x + threadIdx.x;
    if (e < N_EDGES) {
        int pos = atomicAdd(&cursor[dst[e]], 1);
        csrsrc[pos] = src[e];
    }
}

// ---------------- weight prep: transpose + bf16 hi/lo split ----------------
__global__ void k_prep_w(const float* __restrict__ W, __nv_bfloat16* __restrict__ Th,
                         __nv_bfloat16* __restrict__ Tl, int K, int N) {
    int idx = blockIdx.x * blockDim.x + threadIdx.x;
    if (idx >= K * N) return;
    size_t lofs = (size_t)blockIdx.y * K * N;
    int k = idx / N, n = idx % N;
    float v = W[lofs + idx];
    __nv_bfloat16 hi = __float2bfloat16_rn(v);
    float r = v - __bfloat162float(hi);
    Th[lofs + (size_t)n * K + k] = hi;
    Tl[lofs + (size_t)n * K + k] = __float2bfloat16_rn(r);
}

// ---------------- gather aggregation (layer 0: fp32 input) -----------------
__global__ void k_gather_first(const float* __restrict__ x,
                               const int* __restrict__ rowptr,
                               const int* __restrict__ csrsrc,
                               const float* __restrict__ epsp,
                               __nv_bfloat16* __restrict__ oh,
                               __nv_bfloat16* __restrict__ ol) {
    int n = (blockIdx.x * blockDim.x + threadIdx.x) >> 5;
    if (n >= N_NODES) return;
    int lane = threadIdx.x & 31;
    float epsv = 1.0f + __ldg(epsp);
    float4 v = *(const float4*)(x + (size_t)n * C_IN + lane * 4);
    float4 acc;
    acc.x = epsv * v.x; acc.y = epsv * v.y; acc.z = epsv * v.z; acc.w = epsv * v.w;
    int beg = __ldg(rowptr + n), end = __ldg(rowptr + n + 1);
    int e = beg;
    for (; e + 1 < end; e += 2) {
        int s0 = __ldg(csrsrc + e), s1 = __ldg(csrsrc + e + 1);
        float4 a = *(const float4*)(x + (size_t)s0 * C_IN + lane * 4);
        float4 b = *(const float4*)(x + (size_t)s1 * C_IN + lane * 4);
        acc.x += a.x + b.x; acc.y += a.y + b.y;
        acc.z += a.z + b.z; acc.w += a.w + b.w;
    }
    if (e < end) {
        int s0 = __ldg(csrsrc + e);
        float4 a = *(const float4*)(x + (size_t)s0 * C_IN + lane * 4);
        acc.x += a.x; acc.y += a.y; acc.z += a.z; acc.w += a.w;
    }
    float hx = __bfloat162float(__float2bfloat16_rn(acc.x));
    float hy = __bfloat162float(__float2bfloat16_rn(acc.y));
    float hz = __bfloat162float(__float2bfloat16_rn(acc.z));
    float hw = __bfloat162float(__float2bfloat16_rn(acc.w));
    size_t o = (size_t)n * C_IN + lane * 4;
    *(uint2*)(oh + o) = make_uint2(pack_bf2(hx, hy), pack_bf2(hz, hw));
    *(uint2*)(ol + o) = make_uint2(pack_bf2(acc.x - hx, acc.y - hy),
                                   pack_bf2(acc.z - hz, acc.w - hw));
}

// ---------------- gather aggregation (layers 1..3: packed x input) ---------
// packed layout: per node 32 groups of 16B: {hi0,hi1,hi2,hi3,lo0,lo1,lo2,lo3}
__global__ void k_gather_next(const __nv_bfloat16* __restrict__ xp,
                              const int* __restrict__ rowptr,
                              const int* __restrict__ csrsrc,
                              const float* __restrict__ epsp,
                              __nv_bfloat16* __restrict__ oh,
                              __nv_bfloat16* __restrict__ ol) {
    int n = (blockIdx.x * blockDim.x + threadIdx.x) >> 5;
    if (n >= N_NODES) return;
    int lane = threadIdx.x & 31;
    float epsv = 1.0f + __ldg(epsp);
    const uint4* xp4 = (const uint4*)xp;
    uint4 u = __ldg(xp4 + (size_t)n * 32 + lane);
    float2 h0 = unpk(u.x), h1 = unpk(u.y), l0 = unpk(u.z), l1 = unpk(u.w);
    float4 acc;
    acc.x = epsv * (h0.x + l0.x); acc.y = epsv * (h0.y + l0.y);
    acc.z = epsv * (h1.x + l1.x); acc.w = epsv * (h1.y + l1.y);
    int beg = __ldg(rowptr + n), end = __ldg(rowptr + n + 1);
    int e = beg;
    for (; e + 1 < end; e += 2) {
        int s0 = __ldg(csrsrc + e), s1 = __ldg(csrsrc + e + 1);
        uint4 a = __ldg(xp4 + (size_t)s0 * 32 + lane);
        uint4 b = __ldg(xp4 + (size_t)s1 * 32 + lane);
        float2 p0 = unpk(a.x), p1 = unpk(a.y), p2 = unpk(a.z), p3 = unpk(a.w);
        float2 q0 = unpk(b.x), q1 = unpk(b.y), q2 = unpk(b.z), q3 = unpk(b.w);
        acc.x += p0.x + p2.x + q0.x + q2.x;
        acc.y += p0.y + p2.y + q0.y + q2.y;
        acc.z += p1.x + p3.x + q1.x + q3.x;
        acc.w += p1.y + p3.y + q1.y + q3.y;
    }
    if (e < end) {
        int s0 = __ldg(csrsrc + e);
        uint4 a = __ldg(xp4 + (size_t)s0 * 32 + lane);
        float2 p0 = unpk(a.x), p1 = unpk(a.y), p2 = unpk(a.z), p3 = unpk(a.w);
        acc.x += p0.x + p2.x; acc.y += p0.y + p2.y;
        acc.z += p1.x + p3.x; acc.w += p1.y + p3.y;
    }
    float hx = __bfloat162float(__float2bfloat16_rn(acc.x));
    float hy = __bfloat162float(__float2bfloat16_rn(acc.y));
    float hz = __bfloat162float(__float2bfloat16_rn(acc.z));
    float hw = __bfloat162float(__float2bfloat16_rn(acc.w));
    size_t o = (size_t)n * C_IN + lane * 4;
    *(uint2*)(oh + o) = make_uint2(pack_bf2(hx, hy), pack_bf2(hz, hw));
    *(uint2*)(ol + o) = make_uint2(pack_bf2(acc.x - hx, acc.y - hy),
                                   pack_bf2(acc.z - hz, acc.w - hw));
}

// ---------------- cp.async + ldmatrix split-bf16 GEMM -----------------------
// out = relu(bn(A @ Wt^T + bias)); D = Ah*Bh + Al*Bh + Ah*Bl.
// packed_out: write packed hi|lo x layout (for gather/pool); else planar.
#define LDT 40
#define TILE_B (128 * LDT * 2)
#define OFF_AH 0
#define OFF_AL (1 * TILE_B)
#define OFF_BH (2 * TILE_B)
#define OFF_BL (3 * TILE_B)
#define STG (4 * TILE_B)
#define GEMM_SMEM (2 * STG)  // 81920 B

__global__ __launch_bounds__(256)
void k_gemm_mma(const __nv_bfloat16* __restrict__ Ah,
                const __nv_bfloat16* __restrict__ Al,
                const __nv_bfloat16* __restrict__ Bh,
                const __nv_bfloat16* __restrict__ Bl,
                const float* __restrict__ bias,
                const float* __restrict__ bng, const float* __restrict__ bnb,
                const float* __restrict__ bnm, const float* __restrict__ bnv,
                __nv_bfloat16* __restrict__ outh, __nv_bfloat16* __restrict__ outl,
                int M, int Ntot, int K, int packed_out) {
    extern __shared__ __align__(16) char sm[];
    __shared__ float s_sc[128];
    __shared__ float s_sh[128];

    const int tid = threadIdx.x;
    const int wid = tid >> 5;
    const int lane = tid & 31;
    const int warp_m = wid & 3;
    const int warp_n = wid >> 2;
    const int g = lane >> 2;
    const int q = lane & 3;
    const int m0 = blockIdx.x * 128;
    const int n0 = blockIdx.y * 128;
    const uint32_t smb = smem_u32(sm);

    if (tid < 128) {
        int c = n0 + tid;
        float s = __ldg(bng + c) * rsqrtf(__ldg(bnv + c) + BN_EPS);
        s_sc[tid] = s;
        s_sh[tid] = (__ldg(bias + c) - __ldg(bnm + c)) * s + __ldg(bnb + c);
    }

    // per-thread ldmatrix lane offsets (rows via lane&15, k-half via lane>>4)
    const uint32_t a_lm = (uint32_t)((warp_m * 32 + (lane & 15)) * LDT + (lane >> 4) * 8) * 2;
    const uint32_t b_lm = (uint32_t)((warp_n * 64 + (lane & 15)) * LDT + (lane >> 4) * 8) * 2;

    float acc[2][8][4];
#pragma unroll
    for (int mt = 0; mt < 2; mt++)
#pragma unroll
        for (int nt = 0; nt < 8; nt++)
#pragma unroll
            for (int j = 0; j < 4; j++) acc[mt][nt][j] = 0.f;

    const int NCH = K >> 5;

    auto prefetch = [&](int c) {
        const uint32_t base = smb + (c & 1) * STG;
        const int k0 = c << 5;
#pragma unroll
        for (int i = 0; i < 2; ++i) {
            int idx = i * 256 + tid;
            int r = idx >> 2;
            int kc = (idx & 3) * 8;
            uint32_t so = (uint32_t)(r * LDT + kc) * 2;
            int row = m0 + r;
            uint32_t sz = (row < M) ? 16u : 0u;
            size_t ga = (size_t)row * K + k0 + kc;
            cp16(base + OFF_AH + so, Ah + ga, sz);
            cp16(base + OFF_AL + so, Al + ga, sz);
            size_t gb = (size_t)(n0 + r) * K + k0 + kc;
            cp16(base + OFF_BH + so, Bh + gb, 16u);
            cp16(base + OFF_BL + so, Bl + gb, 16u);
        }
    };

    prefetch(0);
    CP_COMMIT();

    for (int c = 0; c < NCH; ++c) {
        if (c + 1 < NCH) {
            prefetch(c + 1);
            CP_COMMIT();
            CP_WAIT(1);
        } else {
            CP_WAIT(0);
        }
        __syncthreads();
        const uint32_t sb = smb + (c & 1) * STG;
#pragma unroll
        for (int ks = 0; ks < 32; ks += 16) {
            uint32_t ah[2][4], al[2][4];
#pragma unroll
            for (int mt = 0; mt < 2; mt++) {
                uint32_t ao = sb + a_lm + (uint32_t)(mt * 16 * LDT + ks) * 2;
                LDSM_X4(ah[mt], ao + OFF_AH);
                LDSM_X4(al[mt], ao + OFF_AL);
            }
#pragma unroll
            for (int p = 0; p < 4; p++) {
                uint32_t bh[4], bl[4];
                uint32_t bo = sb + b_lm + (uint32_t)(p * 16 * LDT + ks) * 2;
                LDSM_X4(bh, bo + OFF_BH);
                LDSM_X4(bl, bo + OFF_BL);
#pragma unroll
                for (int sub = 0; sub < 2; sub++) {
                    int nt = p * 2 + sub;
                    uint32_t b0h = bh[sub], b1h = bh[2 + sub];
                    uint32_t b0l = bl[sub], b1l = bl[2 + sub];
#pragma unroll
                    for (int mt = 0; mt < 2; mt++) {
                        MMA_BF16(acc[mt][nt], ah[mt], b0h, b1h);
                        MMA_BF16(acc[mt][nt], al[mt], b0h, b1h);
                        MMA_BF16(acc[mt][nt], ah[mt], b0l, b1l);
                    }
                }
            }
        }
        __syncthreads();
    }

    // ---- epilogue: bias+BN+ReLU, split to bf16 hi/lo ----
#pragma unroll
    for (int mt = 0; mt < 2; mt++) {
        int rr[2];
        rr[0] = m0 + warp_m * 32 + mt * 16 + g;
        rr[1] = rr[0] + 8;
#pragma unroll
        for (int nt = 0; nt < 8; nt++) {
            int cl = warp_n * 64 + nt * 8 + q * 2;
            float sc0 = s_sc[cl], sc1 = s_sc[cl + 1];
            float sh0 = s_sh[cl], sh1 = s_sh[cl + 1];
            const float* a = acc[mt][nt];
#pragma unroll
            for (int h = 0; h < 2; h++) {
                int r = rr[h];
                if (r >= M) continue;
                float o0 = fmaxf(fmaf(a[2 * h + 0], sc0, sh0), 0.f);
                float o1 = fmaxf(fmaf(a[2 * h + 1], sc1, sh1), 0.f);
                float h0 = __bfloat162float(__float2bfloat16_rn(o0));
                float h1 = __bfloat162float(__float2bfloat16_rn(o1));
                uint32_t uhi = pack_bf2(h0, h1);
                uint32_t ulo = pack_bf2(o0 - h0, o1 - h1);
                if (packed_out) {
                    int c0 = n0 + cl;
                    size_t base = (size_t)r * 256 + (size_t)(c0 >> 2) * 8 + (c0 & 3);
                    *(uint32_t*)(outh + base) = uhi;       // hi slot
                    *(uint32_t*)(outh + base + 4) = ulo;   // lo slot (+4 elems)
                } else {
                    size_t o = (size_t)r * Ntot + n0 + cl;
                    *(uint32_t*)(outh + o) = uhi;
                    *(uint32_t*)(outl + o) = ulo;
                }
            }
        }
    }
}

// ---------------- graph pooling (packed x input) ----------------------------
__global__ void k_pool(const __nv_bfloat16* __restrict__ xp,
                       const int* __restrict__ batch,
                       float* __restrict__ pooled) {
    int n = (blockIdx.x * blockDim.x + threadIdx.x) >> 5;
    if (n >= N_NODES) return;
    int lane = threadIdx.x & 31;
    const uint4* xp4 = (const uint4*)xp;
    uint4 u = __ldg(xp4 + (size_t)n * 32 + lane);
    float2 h0 = unpk(u.x), h1 = unpk(u.y), l0 = unpk(u.z), l1 = unpk(u.w);
    int gph = __ldg(batch + n);
    float* op = pooled + (size_t)gph * HID + lane * 4;
    asm volatile("red.global.add.v4.f32 [%0], {%1,%2,%3,%4};"
                 :: "l"(op), "f"(h0.x + l0.x), "f"(h0.y + l0.y),
                    "f"(h1.x + l1.x), "f"(h1.y + l1.y)
                 : "memory");
}

// ---------------- head ------------------------------------------------------
__global__ void k_head(const float* __restrict__ pooled,
                       const float* __restrict__ lw1, const float* __restrict__ lb1,
                       const float* __restrict__ g3, const float* __restrict__ b3,
                       const float* __restrict__ m3, const float* __restrict__ v3,
                       const float* __restrict__ lw2, const float* __restrict__ lb2,
                       float* __restrict__ out) {
    __shared__ float p[HID];
    __shared__ float h[HID];
    __shared__ float lg[N_OUT];
    __shared__ float red2[2];
    int gph = blockIdx.x;
    int t = threadIdx.x;

    p[t] = pooled[gph * HID + t];
    __syncthreads();

    float acc = __ldg(lb1 + t);
#pragma unroll 8
    for (int k = 0; k < HID; k++) acc = fmaf(p[k], __ldg(lw1 + k * HID + t), acc);
    float s = __ldg(g3 + t) * rsqrtf(__ldg(v3 + t) + BN_EPS);
    acc = (acc - __ldg(m3 + t)) * s + __ldg(b3 + t);
    h[t] = fmaxf(acc, 0.f);
    __syncthreads();

    if (t < N_OUT) {
        float a = __ldg(lb2 + t);
#pragma unroll 8
        for (int k = 0; k < HID; k++) a = fmaf(h[k], __ldg(lw2 + k * N_OUT + t), a);
        lg[t] = a;
    }
    __syncthreads();

    if (t == 0) {
        float mx = lg[0];
        for (int i = 1; i < N_OUT; i++) mx = fmaxf(mx, lg[i]);
        float se = 0.f;
        for (int i = 0; i < N_OUT; i++) se += expf(lg[i] - mx);
        red2[0] = mx;
        red2[1] = logf(se);
    }
    __syncthreads();

    if (t < N_OUT) out[gph * N_OUT + t] = lg[t] - red2[0] - red2[1];
}

// ---------------- host orchestration ----------------------------------------
extern "C" void kernel_launch(void* const* d_in, const int* in_sizes, int n_in,
                              void* d_out, int out_size) {
    const float* x       = (const float*)d_in[0];
    const int*   ei      = (const int*)d_in[1];
    const int*   batch   = (const int*)d_in[2];
    const float* w1      = (const float*)d_in[3];
    const float* b1      = (const float*)d_in[4];
    const float* bn1_g   = (const float*)d_in[5];
    const float* bn1_b   = (const float*)d_in[6];
    const float* bn1_m   = (const float*)d_in[7];
    const float* bn1_v   = (const float*)d_in[8];
    const float* gin_eps = (const float*)d_in[9];
    const float* w2      = (const float*)d_in[10];
    const float* b2      = (const float*)d_in[11];
    const float* bn2_g   = (const float*)d_in[12];
    const float* bn2_b   = (const float*)d_in[13];
    const float* bn2_m   = (const float*)d_in[14];
    const float* bn2_v   = (const float*)d_in[15];
    const float* lin1_w  = (const float*)d_in[16];
    const float* lin1_b  = (const float*)d_in[17];
    const float* bn3_g   = (const float*)d_in[18];
    const float* bn3_b   = (const float*)d_in[19];
    const float* bn3_m   = (const float*)d_in[20];
    const float* bn3_v   = (const float*)d_in[21];
    const float* lin2_w  = (const float*)d_in[22];
    const float* lin2_b  = (const float*)d_in[23];

    __nv_bfloat16 *aggh, *aggl, *h1h, *h1l, *xp;
    __nv_bfloat16 *w1t_hi, *w1t_lo, *w2t_hi, *w2t_lo;
    float* pooled;
    int *deg, *rowptr, *cursor, *bsum, *csrsrc;
    cudaGetSymbolAddress((void**)&aggh, g_aggh);
    cudaGetSymbolAddress((void**)&aggl, g_aggl);
    cudaGetSymbolAddress((void**)&h1h, g_h1h);
    cudaGetSymbolAddress((void**)&h1l, g_h1l);
    cudaGetSymbolAddress((void**)&xp, g_xp);
    cudaGetSymbolAddress((void**)&pooled, g_pooled);
    cudaGetSymbolAddress((void**)&deg, g_deg);
    cudaGetSymbolAddress((void**)&rowptr, g_rowptr);
    cudaGetSymbolAddress((void**)&cursor, g_cursor);
    cudaGetSymbolAddress((void**)&bsum, g_bsum);
    cudaGetSymbolAddress((void**)&csrsrc, g_csrsrc);
    cudaGetSymbolAddress((void**)&w1t_hi, g_w1t_hi);
    cudaGetSymbolAddress((void**)&w1t_lo, g_w1t_lo);
    cudaGetSymbolAddress((void**)&w2t_hi, g_w2t_hi);
    cudaGetSymbolAddress((void**)&w2t_lo, g_w2t_lo);

    cudaFuncSetAttribute(k_gemm_mma, cudaFuncAttributeMaxDynamicSharedMemorySize,
                         GEMM_SMEM);

    const int WSZ = C_IN * 2 * HID;
    const int NB = (N_NODES + 1023) / 1024;

    {
        dim3 gr((WSZ + 255) / 256, N_LAYERS);
        k_prep_w<<<gr, 256>>>(w1, w1t_hi, w1t_lo, C_IN, 2 * HID);
        k_prep_w<<<gr, 256>>>(w2, w2t_hi, w2t_lo, 2 * HID, HID);
    }

    // --- CSR build ---
    k_zero_i<<<(N_NODES + 255) / 256, 256>>>(deg, N_NODES);
    k_hist<<<(N_EDGES + 255) / 256, 256>>>(ei + N_EDGES, deg);
    k_scan_block<<<NB, 1024>>>(deg, rowptr, bsum);
    k_scan_sums<<<1, 32>>>(bsum, NB);
    k_scan_add<<<(N_NODES + 255) / 256, 256>>>(rowptr, bsum, cursor);
    k_scatter<<<(N_EDGES + 255) / 256, 256>>>(ei, ei + N_EDGES, cursor, csrsrc);

    const int MT = (N_NODES + 127) / 128;
    const int GB = (N_NODES * 32 + 255) / 256;

    for (int l = 0; l < N_LAYERS; l++) {
        if (l == 0)
            k_gather_first<<<GB, 256>>>(x, rowptr, csrsrc, gin_eps + l, aggh, aggl);
        else
            k_gather_next<<<GB, 256>>>(xp, rowptr, csrsrc, gin_eps + l, aggh, aggl);
        // GEMM1: [100000,128]@[128,256] -> h1 (planar), BN1+ReLU
        {
            dim3 grid(MT, 2);
            k_gemm_mma<<<grid, 256, GEMM_SMEM>>>(
                aggh, aggl,
                w1t_hi + (size_t)l * WSZ, w1t_lo + (size_t)l * WSZ,
                b1 + (size_t)l * 2 * HID,
                bn1_g + (size_t)l * 2 * HID, bn1_b + (size_t)l * 2 * HID,
                bn1_m + (size_t)l * 2 * HID, bn1_v + (size_t)l * 2 * HID,
                h1h, h1l, N_NODES, 2 * HID, C_IN, 0);
        }
        // GEMM2: [100000,256]@[256,128] -> x packed, BN2+ReLU
        {
            dim3 grid(MT, 1);
            k_gemm_mma<<<grid, 256, GEMM_SMEM>>>(
                h1h, h1l,
                w2t_hi + (size_t)l * WSZ, w2t_lo + (size_t)l * WSZ,
                b2 + (size_t)l * HID,
                bn2_g + (size_t)l * HID, bn2_b + (size_t)l * HID,
                bn2_m + (size_t)l * HID, bn2_v + (size_t)l * HID,
                xp, nullptr, N_NODES, HID, 2 * HID, 1);
        }
    }

    k_zero_f4<<<(N_GRAPHS * HID / 4 + 255) / 256, 256>>>((float4*)pooled,
                                                         N_GRAPHS * HID / 4);
    k_pool<<<GB, 256>>>(xp, batch, pooled);
    k_head<<<N_GRAPHS, HID>>>(pooled, lin1_w, lin1_b,
                              bn3_g, bn3_b, bn3_m, bn3_v,
                              lin2_w, lin2_b, (float*)d_out);
}